// round 2
// baseline (speedup 1.0000x reference)
#include <cuda_runtime.h>
#include <cstdint>

#define DEV static __device__ __forceinline__

static constexpr int B_ = 4, N_ = 256, D_ = 128, L_ = 3, BN = 1024;

// ---------------- scratch (device globals) ----------------
__device__ float g_P[BN * 384];            // [Pi | Pj | Pn] per row
__device__ float g_aggH[2][BN * D_];       // j-half partial aggregations
__device__ float g_rs[BN];                 // rowsum(adj)
__device__ float g_Wc[L_][D_ * D_];        // ew2 @ nw1b
__device__ float g_cb[L_][D_];             // eb2 @ nw1b
__device__ float g_adj2[B_ * N_ * 2 * N_]; // [b][j][2*i] duplicated adjacency

// ---------------- f32x2 helpers ----------------
typedef unsigned long long u64;
DEV u64 pk(float lo, float hi) {
    u64 r; asm("mov.b64 %0,{%1,%2};" : "=l"(r) : "f"(lo), "f"(hi)); return r;
}
DEV void upk(u64 v, float& lo, float& hi) {
    asm("mov.b64 {%0,%1},%2;" : "=f"(lo), "=f"(hi) : "l"(v));
}
DEV u64 add2(u64 a, u64 b) {
    u64 r; asm("add.rn.f32x2 %0,%1,%2;" : "=l"(r) : "l"(a), "l"(b)); return r;
}
DEV u64 fma2(u64 a, u64 b, u64 c) {
    u64 r; asm("fma.rn.f32x2 %0,%1,%2,%3;" : "=l"(r) : "l"(a), "l"(b), "l"(c)); return r;
}
DEV u64 relu2(u64 v) {
    float lo, hi; upk(v, lo, hi);
    return pk(fmaxf(lo, 0.f), fmaxf(hi, 0.f));
}

// ---------------- merged setup kernel ----------------
// blocks [0,1024): adj dup   [1024,1152): rowsum   [1152,1176): Wc/cb
__global__ void k_setup(const float* __restrict__ adj, const float* __restrict__ ew2,
                        const float* __restrict__ eb2, const float* __restrict__ nw1) {
    int blk = blockIdx.x, tid = threadIdx.x;
    if (blk < 1024) {
        int idx = blk * 256 + tid;               // j fastest
        int j = idx & 255, i = (idx >> 8) & 255, b = idx >> 16;
        float v = adj[idx];
        float* dst = g_adj2 + ((b * N_ + j) * 2 * N_) + 2 * i;
        dst[0] = v; dst[1] = v;
    } else if (blk < 1152) {
        int w = (blk - 1024) * 8 + (tid >> 5);   // one warp per row
        int lane = tid & 31;
        const float* row = adj + w * N_;
        float s = 0.f;
#pragma unroll
        for (int j = lane; j < N_; j += 32) s += row[j];
#pragma unroll
        for (int o = 16; o; o >>= 1) s += __shfl_xor_sync(~0u, s, o);
        if (!lane) g_rs[w] = s;
    } else if (tid < 128) {
        int q = blk - 1152;
        int l = q >> 3, rblk = q & 7;
        int k = tid;
        const float* w2 = ew2 + l * D_ * D_ + rblk * 16 * D_;
        const float* n1b = nw1 + l * 2 * D_ * D_ + D_ * D_;
        const float* b2 = eb2 + l * D_;
        float acc[16];
#pragma unroll
        for (int r = 0; r < 16; r++) acc[r] = 0.f;
        float accb = 0.f;
#pragma unroll 4
        for (int m = 0; m < D_; m++) {
            float wv = n1b[m * D_ + k];
#pragma unroll
            for (int r = 0; r < 16; r++) acc[r] = fmaf(w2[r * D_ + m], wv, acc[r]);
            if (rblk == 0) accb = fmaf(b2[m], wv, accb);
        }
#pragma unroll
        for (int r = 0; r < 16; r++) g_Wc[l][(rblk * 16 + r) * D_ + k] = acc[r];
        if (rblk == 0) g_cb[l][k] = accb;
    }
}

// ---------------- K1: P = x @ [ew1a | ew1b | nw1a] (+biases) ----------------
// grid (64 rowblocks, 3 cblk), 128 threads. Thread tile 4 rows x 4 cols.
// Warp-uniform row-group: A rows come from one broadcast LDS.128 per k;
// W streamed via coalesced LDG.128 (L1-resident), no smem staging.
__global__ void __launch_bounds__(128) k_proj(
        const float* __restrict__ x, const float* __restrict__ ew1,
        const float* __restrict__ nw1, const float* __restrict__ eb1,
        const float* __restrict__ nb1, int l) {
    __shared__ float ATs[128 * 20];  // [k][row(16)+pad4], pairs of rows packed
    int rb = blockIdx.x, cblk = blockIdx.y;
    int tid = threadIdx.x;

    const float* W; const float* bias = nullptr;
    if (cblk == 0)      { W = ew1 + l * 2 * D_ * D_;            bias = eb1 + l * D_; }
    else if (cblk == 1) { W = ew1 + l * 2 * D_ * D_ + D_ * D_; }
    else                { W = nw1 + l * 2 * D_ * D_;            bias = nb1 + l * D_; }

    const float* Arows = x + rb * 16 * D_;
    for (int idx = tid; idx < 16 * 128; idx += 128) {
        int r = idx >> 7, k = idx & 127;
        ATs[k * 20 + r] = Arows[idx];
    }
    __syncthreads();

    int cg = tid & 31, rg = tid >> 5;          // warp == rg (broadcast LDS)
    const float* ap = ATs + rg * 4;
    const float* wp = W + cg * 4;
    u64 acc[2][4] = {};
#pragma unroll 4
    for (int k = 0; k < 128; k++) {
        ulonglong2 a = *(const ulonglong2*)(ap + k * 20);   // rows (0,1),(2,3)
        float4 w = __ldg((const float4*)(wp + k * 128));
        u64 w0 = pk(w.x, w.x), w1 = pk(w.y, w.y), w2 = pk(w.z, w.z), w3 = pk(w.w, w.w);
        acc[0][0] = fma2(a.x, w0, acc[0][0]);
        acc[0][1] = fma2(a.x, w1, acc[0][1]);
        acc[0][2] = fma2(a.x, w2, acc[0][2]);
        acc[0][3] = fma2(a.x, w3, acc[0][3]);
        acc[1][0] = fma2(a.y, w0, acc[1][0]);
        acc[1][1] = fma2(a.y, w1, acc[1][1]);
        acc[1][2] = fma2(a.y, w2, acc[1][2]);
        acc[1][3] = fma2(a.y, w3, acc[1][3]);
    }

    float4 bv = make_float4(0.f, 0.f, 0.f, 0.f);
    if (bias) bv = *(const float4*)(bias + cg * 4);
    float* base = g_P + (rb * 16 + rg * 4) * 384 + cblk * 128 + cg * 4;
#pragma unroll
    for (int p = 0; p < 2; p++) {
        float v0[4], v1[4];
#pragma unroll
        for (int c = 0; c < 4; c++) upk(acc[p][c], v0[c], v1[c]);
        float4 o0 = make_float4(v0[0] + bv.x, v0[1] + bv.y, v0[2] + bv.z, v0[3] + bv.w);
        float4 o1 = make_float4(v1[0] + bv.x, v1[1] + bv.y, v1[2] + bv.z, v1[3] + bv.w);
        *(float4*)(base + (2 * p) * 384) = o0;
        *(float4*)(base + (2 * p + 1) * 384) = o1;
    }
}

// ---------------- K2: aggH[jh][b,i,:] = sum_{j half} adj * relu(Pi + Pj) ----------------
// grid (64 = b*16+iblk, 2 jhalf), 256 threads (8 warps x 2 i's, lane = 4 d's)
__global__ void __launch_bounds__(256) k_agg() {
    extern __shared__ float sm[];
    float* Pjs = sm;             // [128 j][128 d]  64KB
    float* adj2s = sm + 16384;   // [128 j][32]     16KB (dup adj pairs, 16 i's)
    int b = blockIdx.x >> 4, iblk = blockIdx.x & 15, jh = blockIdx.y;
    int tid = threadIdx.x;
    int ibase = iblk * 16, jbase = jh * 128;

    for (int idx = tid; idx < 4096; idx += 256) {
        int jj = idx >> 5, d4 = idx & 31;
        ((float4*)(Pjs + jj * 128))[d4] =
            *(const float4*)(g_P + (b * 256 + jbase + jj) * 384 + 128 + d4 * 4);
    }
    for (int idx = tid; idx < 1024; idx += 256) {
        int jj = idx >> 3, c4 = idx & 7;
        ((float4*)(adj2s + jj * 32))[c4] =
            *(const float4*)(g_adj2 + (b * 256 + jbase + jj) * 512 + 2 * ibase + c4 * 4);
    }
    __syncthreads();

    int lane = tid & 31, w = tid >> 5;
    int d0 = lane * 4;
    int i0 = b * 256 + ibase + w * 2;
    u64 xi[2][2];
#pragma unroll
    for (int q = 0; q < 2; q++) {
        ulonglong2 v = *(const ulonglong2*)(g_P + (i0 + q) * 384 + d0);
        xi[q][0] = v.x; xi[q][1] = v.y;
    }
    u64 acc[2][2] = {};
    const float* pj = Pjs + d0;
    const float* ad = adj2s + w * 4;    // 16B = {dup(adj_i0), dup(adj_i1)}
#pragma unroll 4
    for (int jj = 0; jj < 128; jj++) {
        ulonglong2 xj = *(const ulonglong2*)(pj + jj * 128);
        ulonglong2 aa = *(const ulonglong2*)(ad + jj * 32);
        u64 t;
        t = relu2(add2(xi[0][0], xj.x)); acc[0][0] = fma2(t, aa.x, acc[0][0]);
        t = relu2(add2(xi[0][1], xj.y)); acc[0][1] = fma2(t, aa.x, acc[0][1]);
        t = relu2(add2(xi[1][0], xj.x)); acc[1][0] = fma2(t, aa.y, acc[1][0]);
        t = relu2(add2(xi[1][1], xj.y)); acc[1][1] = fma2(t, aa.y, acc[1][1]);
    }
#pragma unroll
    for (int q = 0; q < 2; q++) {
        ulonglong2 st; st.x = acc[q][0]; st.y = acc[q][1];
        *(ulonglong2*)(g_aggH[jh] + (i0 + q) * 128 + d0) = st;
    }
}

// ---------------- K3: nh = relu(Pn + (aggH0+aggH1)@Wc + rs*cb); x += nh@nw2 + nb2 ----------------
// grid 128 (8 rows each), 128 threads. Thread tile 4 rows x 2 cols, two chained GEMMs.
__global__ void __launch_bounds__(128) k_node(
        float* __restrict__ x, const float* __restrict__ nw2,
        const float* __restrict__ nb2, int l) {
    __shared__ float ATs[128 * 12];  // [k][8 rows + pad]
    __shared__ float NTs[128 * 12];
    int rb = blockIdx.x;
    int tid = threadIdx.x;
    int cg = tid & 63, rg = tid >> 6;          // warp: uniform rg -> broadcast LDS

    for (int idx = tid; idx < 8 * 128; idx += 128) {
        int r = idx >> 7, k = idx & 127;
        int row = rb * 8 + r;
        ATs[k * 12 + r] = g_aggH[0][row * 128 + k] + g_aggH[1][row * 128 + k];
    }
    __syncthreads();

    const float* Wc = g_Wc[l];
    const float* ap = ATs + rg * 4;
    u64 acc[2][2] = {};
#pragma unroll 4
    for (int k = 0; k < 128; k++) {
        ulonglong2 a = *(const ulonglong2*)(ap + k * 12);
        float2 w = __ldg((const float2*)(Wc + k * 128 + cg * 2));
        u64 w0 = pk(w.x, w.x), w1 = pk(w.y, w.y);
        acc[0][0] = fma2(a.x, w0, acc[0][0]);
        acc[0][1] = fma2(a.x, w1, acc[0][1]);
        acc[1][0] = fma2(a.y, w0, acc[1][0]);
        acc[1][1] = fma2(a.y, w1, acc[1][1]);
    }

    float cb0 = g_cb[l][2 * cg], cb1 = g_cb[l][2 * cg + 1];
#pragma unroll
    for (int p = 0; p < 2; p++) {
        int rloc = rg * 4 + 2 * p;
        int row = rb * 8 + rloc;
        float2 pn0 = *(const float2*)(g_P + row * 384 + 256 + 2 * cg);
        float2 pn1 = *(const float2*)(g_P + (row + 1) * 384 + 256 + 2 * cg);
        float rs0 = g_rs[row], rs1 = g_rs[row + 1];
        float v00, v10, v01, v11;
        upk(acc[p][0], v00, v10);
        upk(acc[p][1], v01, v11);
        v00 = fmaxf(fmaf(rs0, cb0, v00 + pn0.x), 0.f);
        v01 = fmaxf(fmaf(rs0, cb1, v01 + pn0.y), 0.f);
        v10 = fmaxf(fmaf(rs1, cb0, v10 + pn1.x), 0.f);
        v11 = fmaxf(fmaf(rs1, cb1, v11 + pn1.y), 0.f);
        NTs[(2 * cg) * 12 + rloc] = v00;
        NTs[(2 * cg + 1) * 12 + rloc] = v01;
        NTs[(2 * cg) * 12 + rloc + 1] = v10;
        NTs[(2 * cg + 1) * 12 + rloc + 1] = v11;
    }
    __syncthreads();

    const float* W2 = nw2 + l * D_ * D_;
    const float* np = NTs + rg * 4;
    u64 acc2[2][2] = {};
#pragma unroll 4
    for (int k = 0; k < 128; k++) {
        ulonglong2 a = *(const ulonglong2*)(np + k * 12);
        float2 w = __ldg((const float2*)(W2 + k * 128 + cg * 2));
        u64 w0 = pk(w.x, w.x), w1 = pk(w.y, w.y);
        acc2[0][0] = fma2(a.x, w0, acc2[0][0]);
        acc2[0][1] = fma2(a.x, w1, acc2[0][1]);
        acc2[1][0] = fma2(a.y, w0, acc2[1][0]);
        acc2[1][1] = fma2(a.y, w1, acc2[1][1]);
    }

    float b0 = nb2[l * D_ + 2 * cg], b1 = nb2[l * D_ + 2 * cg + 1];
#pragma unroll
    for (int p = 0; p < 2; p++) {
        int row = rb * 8 + rg * 4 + 2 * p;
        float v00, v10, v01, v11;
        upk(acc2[p][0], v00, v10);
        upk(acc2[p][1], v01, v11);
        float2* x0 = (float2*)(x + row * D_ + 2 * cg);
        float2* x1 = (float2*)(x + (row + 1) * D_ + 2 * cg);
        float2 o0 = *x0, o1 = *x1;
        o0.x += v00 + b0; o0.y += v01 + b1;
        o1.x += v10 + b0; o1.y += v11 + b1;
        *x0 = o0; *x1 = o1;
    }
}

// ---------------- launch ----------------
extern "C" void kernel_launch(void* const* d_in, const int* in_sizes, int n_in,
                              void* d_out, int out_size) {
    const float* nf  = (const float*)d_in[0];
    const float* adj = (const float*)d_in[1];
    const float* ew1 = (const float*)d_in[2];
    const float* eb1 = (const float*)d_in[3];
    const float* ew2 = (const float*)d_in[4];
    const float* eb2 = (const float*)d_in[5];
    const float* nw1 = (const float*)d_in[6];
    const float* nb1 = (const float*)d_in[7];
    const float* nw2 = (const float*)d_in[8];
    const float* nb2 = (const float*)d_in[9];
    float* x = (float*)d_out;

    const int SM_AGG = (16384 + 4096) * 4;  // 81920
    cudaFuncSetAttribute(k_agg, cudaFuncAttributeMaxDynamicSharedMemorySize, SM_AGG);

    k_setup<<<1176, 256>>>(adj, ew2, eb2, nw1);
    cudaMemcpyAsync(x, nf, (size_t)BN * D_ * sizeof(float), cudaMemcpyDeviceToDevice, 0);

    for (int l = 0; l < L_; l++) {
        k_proj<<<dim3(64, 3), 128>>>(x, ew1, nw1, eb1, nb1, l);
        k_agg<<<dim3(64, 2), 256, SM_AGG>>>();
        k_node<<<128, 128>>>(x, nw2, nb2, l);
    }
}

// round 3
// speedup vs baseline: 1.0024x; 1.0024x over previous
#include <cuda_runtime.h>
#include <cstdint>

#define DEV static __device__ __forceinline__

static constexpr int B_ = 4, N_ = 256, D_ = 128, L_ = 3, BN = 1024;

// ---------------- scratch (device globals) ----------------
__device__ float g_P[BN * 384];            // [Pi | Pj | Pn] per row
__device__ float g_aggH[4][BN * D_];       // j-quarter partial aggregations
__device__ float g_NH[BN * D_];            // node-MLP hidden
__device__ float g_rs[BN];                 // rowsum(adj)
__device__ float g_Wc[L_][D_ * D_];        // ew2 @ nw1b
__device__ float g_cb[L_][D_];             // eb2 @ nw1b
__device__ float g_adj2[B_ * N_ * 2 * N_]; // [b][j][2*i] duplicated adjacency

// ---------------- f32x2 helpers ----------------
typedef unsigned long long u64;
DEV u64 pk(float lo, float hi) {
    u64 r; asm("mov.b64 %0,{%1,%2};" : "=l"(r) : "f"(lo), "f"(hi)); return r;
}
DEV void upk(u64 v, float& lo, float& hi) {
    asm("mov.b64 {%0,%1},%2;" : "=f"(lo), "=f"(hi) : "l"(v));
}
DEV u64 add2(u64 a, u64 b) {
    u64 r; asm("add.rn.f32x2 %0,%1,%2;" : "=l"(r) : "l"(a), "l"(b)); return r;
}
DEV u64 fma2(u64 a, u64 b, u64 c) {
    u64 r; asm("fma.rn.f32x2 %0,%1,%2,%3;" : "=l"(r) : "l"(a), "l"(b), "l"(c)); return r;
}
DEV u64 relu2(u64 v) {
    float lo, hi; upk(v, lo, hi);
    return pk(fmaxf(lo, 0.f), fmaxf(hi, 0.f));
}

// ---------------- merged setup kernel ----------------
// blocks [0,1024): adj dup   [1024,1152): rowsum   [1152,1176): Wc/cb
__global__ void k_setup(const float* __restrict__ adj, const float* __restrict__ ew2,
                        const float* __restrict__ eb2, const float* __restrict__ nw1) {
    int blk = blockIdx.x, tid = threadIdx.x;
    if (blk < 1024) {
        int idx = blk * 256 + tid;               // j fastest
        int j = idx & 255, i = (idx >> 8) & 255, b = idx >> 16;
        float v = adj[idx];
        float* dst = g_adj2 + ((b * N_ + j) * 2 * N_) + 2 * i;
        dst[0] = v; dst[1] = v;
    } else if (blk < 1152) {
        int w = (blk - 1024) * 8 + (tid >> 5);   // one warp per row
        int lane = tid & 31;
        const float* row = adj + w * N_;
        float s = 0.f;
#pragma unroll
        for (int j = lane; j < N_; j += 32) s += row[j];
#pragma unroll
        for (int o = 16; o; o >>= 1) s += __shfl_xor_sync(~0u, s, o);
        if (!lane) g_rs[w] = s;
    } else if (tid < 128) {
        int q = blk - 1152;
        int l = q >> 3, rblk = q & 7;
        int k = tid;
        const float* w2 = ew2 + l * D_ * D_ + rblk * 16 * D_;
        const float* n1b = nw1 + l * 2 * D_ * D_ + D_ * D_;
        const float* b2 = eb2 + l * D_;
        float acc[16];
#pragma unroll
        for (int r = 0; r < 16; r++) acc[r] = 0.f;
        float accb = 0.f;
#pragma unroll 4
        for (int m = 0; m < D_; m++) {
            float wv = n1b[m * D_ + k];
#pragma unroll
            for (int r = 0; r < 16; r++) acc[r] = fmaf(w2[r * D_ + m], wv, acc[r]);
            if (rblk == 0) accb = fmaf(b2[m], wv, accb);
        }
#pragma unroll
        for (int r = 0; r < 16; r++) g_Wc[l][(rblk * 16 + r) * D_ + k] = acc[r];
        if (rblk == 0) g_cb[l][k] = accb;
    }
}

// ============ dup-A GEMM core ============
// CTA: 8 rows x 128 cols, 128 threads (4 warps x 2 rows, lane = 4 cols).
// ATs[k][2r] holds DUPLICATED row values so one broadcast LDS.128 yields two
// f32x2 A operands; W streamed as ulonglong2 LDG.128 -> (c0,c1),(c2,c3) pairs.
// Inner loop: 2 loads + 4 FFMA2, zero MOVs.
struct Acc4 { u64 a00, a01, a10, a11; };  // [row 0/1][colpair 01/23]

DEV Acc4 gemm8(const float* __restrict__ ATs, const float* __restrict__ W, int tid) {
    int lane = tid & 31, wid = tid >> 5;
    const float* ap = ATs + wid * 4;   // 2 dup'd rows = 16B
    const float* wp = W + lane * 4;
    Acc4 acc; acc.a00 = acc.a01 = acc.a10 = acc.a11 = 0ull;
#pragma unroll 8
    for (int k = 0; k < 128; k++) {
        ulonglong2 a = *(const ulonglong2*)(ap + k * 20);              // (r0 dup, r1 dup)
        ulonglong2 w = __ldg((const ulonglong2*)(wp + k * 128));       // ((c0,c1),(c2,c3))
        acc.a00 = fma2(a.x, w.x, acc.a00);
        acc.a01 = fma2(a.x, w.y, acc.a01);
        acc.a10 = fma2(a.y, w.x, acc.a10);
        acc.a11 = fma2(a.y, w.y, acc.a11);
    }
    return acc;
}

// ---------------- K1: P = x @ [ew1a | ew1b | nw1a] (+biases) ----------------
// grid (128 rowblocks, 3 cblk), 128 threads
__global__ void __launch_bounds__(128) k_proj(
        const float* __restrict__ x, const float* __restrict__ ew1,
        const float* __restrict__ nw1, const float* __restrict__ eb1,
        const float* __restrict__ nb1, int l) {
    __shared__ float ATs[128 * 20];
    int rb = blockIdx.x, cblk = blockIdx.y;
    int tid = threadIdx.x;

    const float* W; const float* bias = nullptr;
    if (cblk == 0)      { W = ew1 + l * 2 * D_ * D_;            bias = eb1 + l * D_; }
    else if (cblk == 1) { W = ew1 + l * 2 * D_ * D_ + D_ * D_; }
    else                { W = nw1 + l * 2 * D_ * D_;            bias = nb1 + l * D_; }

    const float* Arows = x + rb * 8 * D_;
    for (int idx = tid; idx < 8 * 128; idx += 128) {
        int r = idx >> 7, k = idx & 127;
        float v = Arows[idx];
        ATs[k * 20 + 2 * r] = v;
        ATs[k * 20 + 2 * r + 1] = v;
    }
    __syncthreads();

    Acc4 acc = gemm8(ATs, W, tid);

    int lane = tid & 31, wid = tid >> 5;
    u64 b01 = 0ull, b23 = 0ull;
    if (bias) {
        ulonglong2 bv = *(const ulonglong2*)(bias + lane * 4);
        b01 = bv.x; b23 = bv.y;
    }
    int row0 = rb * 8 + wid * 2;
    float* base = g_P + row0 * 384 + cblk * 128 + lane * 4;
    ulonglong2 o0, o1;
    o0.x = add2(acc.a00, b01); o0.y = add2(acc.a01, b23);
    o1.x = add2(acc.a10, b01); o1.y = add2(acc.a11, b23);
    *(ulonglong2*)base = o0;
    *(ulonglong2*)(base + 384) = o1;
}

// ---------------- K2: aggH[jq][b,i,:] = sum_{j in quarter} adj * relu(Pi + Pj) ----------------
// grid (64 = b*16+iblk, 4 jq), 256 threads (8 warps x 2 i's, lane = 4 d's)
__global__ void __launch_bounds__(256) k_agg() {
    __shared__ float Pjs[64 * 128];    // 32KB
    __shared__ float adj2s[64 * 32];   // 8KB (dup adj pairs for 16 i's)
    int b = blockIdx.x >> 4, iblk = blockIdx.x & 15, jq = blockIdx.y;
    int tid = threadIdx.x;
    int ibase = iblk * 16, jbase = jq * 64;

    for (int idx = tid; idx < 2048; idx += 256) {
        int jj = idx >> 5, d4 = idx & 31;
        ((float4*)(Pjs + jj * 128))[d4] =
            *(const float4*)(g_P + (b * 256 + jbase + jj) * 384 + 128 + d4 * 4);
    }
    for (int idx = tid; idx < 512; idx += 256) {
        int jj = idx >> 3, c4 = idx & 7;
        ((float4*)(adj2s + jj * 32))[c4] =
            *(const float4*)(g_adj2 + (b * 256 + jbase + jj) * 512 + 2 * ibase + c4 * 4);
    }
    __syncthreads();

    int lane = tid & 31, w = tid >> 5;
    int d0 = lane * 4;
    int i0 = b * 256 + ibase + w * 2;
    u64 xi[2][2];
#pragma unroll
    for (int q = 0; q < 2; q++) {
        ulonglong2 v = *(const ulonglong2*)(g_P + (i0 + q) * 384 + d0);
        xi[q][0] = v.x; xi[q][1] = v.y;
    }
    u64 acc[2][2] = {};
    const float* pj = Pjs + d0;
    const float* ad = adj2s + w * 4;
#pragma unroll 8
    for (int jj = 0; jj < 64; jj++) {
        ulonglong2 xj = *(const ulonglong2*)(pj + jj * 128);
        ulonglong2 aa = *(const ulonglong2*)(ad + jj * 32);   // (dup adj_i0, dup adj_i1)
        u64 t;
        t = relu2(add2(xi[0][0], xj.x)); acc[0][0] = fma2(t, aa.x, acc[0][0]);
        t = relu2(add2(xi[0][1], xj.y)); acc[0][1] = fma2(t, aa.x, acc[0][1]);
        t = relu2(add2(xi[1][0], xj.x)); acc[1][0] = fma2(t, aa.y, acc[1][0]);
        t = relu2(add2(xi[1][1], xj.y)); acc[1][1] = fma2(t, aa.y, acc[1][1]);
    }
#pragma unroll
    for (int q = 0; q < 2; q++) {
        ulonglong2 st; st.x = acc[q][0]; st.y = acc[q][1];
        *(ulonglong2*)(g_aggH[jq] + (i0 + q) * 128 + d0) = st;
    }
}

// ---------------- K3a: NH = relu(Pn + agg@Wc + rs*cb) ----------------
// grid 128 (8 rows each), 128 threads
__global__ void __launch_bounds__(128) k_nh(int l) {
    __shared__ float ATs[128 * 20];
    int rb = blockIdx.x, tid = threadIdx.x;

    for (int idx = tid; idx < 8 * 128; idx += 128) {
        int r = idx >> 7, k = idx & 127;
        int off = (rb * 8 + r) * 128 + k;
        float v = g_aggH[0][off] + g_aggH[1][off] + g_aggH[2][off] + g_aggH[3][off];
        ATs[k * 20 + 2 * r] = v;
        ATs[k * 20 + 2 * r + 1] = v;
    }
    __syncthreads();

    Acc4 acc = gemm8(ATs, g_Wc[l], tid);

    int lane = tid & 31, wid = tid >> 5;
    int row0 = rb * 8 + wid * 2;
    ulonglong2 cb = *(const ulonglong2*)(g_cb[l] + lane * 4);
    float rs0 = g_rs[row0], rs1 = g_rs[row0 + 1];
    u64 rs0p = pk(rs0, rs0), rs1p = pk(rs1, rs1);
    ulonglong2 pn0 = *(const ulonglong2*)(g_P + row0 * 384 + 256 + lane * 4);
    ulonglong2 pn1 = *(const ulonglong2*)(g_P + (row0 + 1) * 384 + 256 + lane * 4);

    ulonglong2 o0, o1;
    o0.x = relu2(fma2(rs0p, cb.x, add2(acc.a00, pn0.x)));
    o0.y = relu2(fma2(rs0p, cb.y, add2(acc.a01, pn0.y)));
    o1.x = relu2(fma2(rs1p, cb.x, add2(acc.a10, pn1.x)));
    o1.y = relu2(fma2(rs1p, cb.y, add2(acc.a11, pn1.y)));
    *(ulonglong2*)(g_NH + row0 * 128 + lane * 4) = o0;
    *(ulonglong2*)(g_NH + (row0 + 1) * 128 + lane * 4) = o1;
}

// ---------------- K3b: x += NH @ nw2 + nb2 ----------------
// grid 128 (8 rows each), 128 threads
__global__ void __launch_bounds__(128) k_upd(
        float* __restrict__ x, const float* __restrict__ nw2,
        const float* __restrict__ nb2, int l) {
    __shared__ float ATs[128 * 20];
    int rb = blockIdx.x, tid = threadIdx.x;

    const float* Arows = g_NH + rb * 8 * 128;
    for (int idx = tid; idx < 8 * 128; idx += 128) {
        int r = idx >> 7, k = idx & 127;
        float v = Arows[idx];
        ATs[k * 20 + 2 * r] = v;
        ATs[k * 20 + 2 * r + 1] = v;
    }
    __syncthreads();

    Acc4 acc = gemm8(ATs, nw2 + l * D_ * D_, tid);

    int lane = tid & 31, wid = tid >> 5;
    int row0 = rb * 8 + wid * 2;
    ulonglong2 bv = *(const ulonglong2*)(nb2 + l * D_ + lane * 4);
    float* p0 = x + row0 * D_ + lane * 4;
    float* p1 = p0 + D_;
    ulonglong2 x0 = *(ulonglong2*)p0;
    ulonglong2 x1 = *(ulonglong2*)p1;
    x0.x = add2(x0.x, add2(acc.a00, bv.x));
    x0.y = add2(x0.y, add2(acc.a01, bv.y));
    x1.x = add2(x1.x, add2(acc.a10, bv.x));
    x1.y = add2(x1.y, add2(acc.a11, bv.y));
    *(ulonglong2*)p0 = x0;
    *(ulonglong2*)p1 = x1;
}

// ---------------- launch ----------------
extern "C" void kernel_launch(void* const* d_in, const int* in_sizes, int n_in,
                              void* d_out, int out_size) {
    const float* nf  = (const float*)d_in[0];
    const float* adj = (const float*)d_in[1];
    const float* ew1 = (const float*)d_in[2];
    const float* eb1 = (const float*)d_in[3];
    const float* ew2 = (const float*)d_in[4];
    const float* eb2 = (const float*)d_in[5];
    const float* nw1 = (const float*)d_in[6];
    const float* nb1 = (const float*)d_in[7];
    const float* nw2 = (const float*)d_in[8];
    const float* nb2 = (const float*)d_in[9];
    float* x = (float*)d_out;

    k_setup<<<1176, 256>>>(adj, ew2, eb2, nw1);
    cudaMemcpyAsync(x, nf, (size_t)BN * D_ * sizeof(float), cudaMemcpyDeviceToDevice, 0);

    for (int l = 0; l < L_; l++) {
        k_proj<<<dim3(128, 3), 128>>>(x, ew1, nw1, eb1, nb1, l);
        k_agg<<<dim3(64, 4), 256>>>();
        k_nh<<<128, 128>>>(l);
        k_upd<<<128, 128>>>(x, nw2, nb2, l);
    }
}

// round 4
// speedup vs baseline: 3.1890x; 3.1813x over previous
#include <cuda_runtime.h>
#include <cstdint>

typedef unsigned long long u64;
#define DEV static __device__ __forceinline__

static constexpr int D_ = 128, L_ = 3;
static constexpr int NB = 128;   // grid: 128 CTAs, 8 rows each (1024 rows)
static constexpr int NT = 512;   // 16 warps

// ---------------- device globals ----------------
__device__ float g_P[2][1024 * 128];   // double-buffered Pj
__device__ float g_Wc[L_][128 * 128];  // ew2 @ nw1b
__device__ float g_cb[L_][128];        // eb2 @ nw1b
__device__ unsigned g_bar[4];          // monotonic barrier counters (replay-safe)

// ---------------- f32x2 helpers ----------------
DEV u64 pk(float lo, float hi) {
    u64 r; asm("mov.b64 %0,{%1,%2};" : "=l"(r) : "f"(lo), "f"(hi)); return r;
}
DEV void upk(u64 v, float& lo, float& hi) {
    asm("mov.b64 {%0,%1},%2;" : "=f"(lo), "=f"(hi) : "l"(v));
}
DEV u64 add2(u64 a, u64 b) {
    u64 r; asm("add.rn.f32x2 %0,%1,%2;" : "=l"(r) : "l"(a), "l"(b)); return r;
}
DEV u64 fma2(u64 a, u64 b, u64 c) {
    u64 r; asm("fma.rn.f32x2 %0,%1,%2,%3;" : "=l"(r) : "l"(a), "l"(b), "l"(c)); return r;
}
DEV u64 relu2(u64 v) {
    float lo, hi; upk(v, lo, hi);
    return pk(fmaxf(lo, 0.f), fmaxf(hi, 0.f));
}

// ---------------- grid barrier (monotonic counter; replay-safe) ----------------
DEV unsigned ld_acq(const unsigned* p) {
    unsigned v;
    asm volatile("ld.acquire.gpu.global.u32 %0,[%1];" : "=r"(v) : "l"(p) : "memory");
    return v;
}
DEV void grid_barrier(int bidx, int tid) {
    __syncthreads();
    if (tid == 0) {
        __threadfence();
        unsigned t = atomicAdd(&g_bar[bidx], 1u);
        unsigned target = (t / (unsigned)NB + 1u) * (unsigned)NB;
        while (ld_acq(&g_bar[bidx]) < target) { __nanosleep(64); }
        __threadfence();
    }
    __syncthreads();
}

// ---------------- GEMM cores (dup-A: one bcast LDS.128 -> two f32x2 A ops) ----------------
struct Acc4 { u64 a00, a01, a10, a11; };

// full-K (128) with 128-thread team: 4 warps x 2 rows, lane = 4 cols
DEV Acc4 gemm8(const float* __restrict__ ATs, const float* __restrict__ W, int ttid) {
    const float* ap = ATs + (ttid >> 5) * 4;
    const float* wp = W + (ttid & 31) * 4;
    Acc4 acc; acc.a00 = acc.a01 = acc.a10 = acc.a11 = 0ull;
#pragma unroll 8
    for (int k = 0; k < 128; k++) {
        ulonglong2 a = *(const ulonglong2*)(ap + k * 20);
        ulonglong2 w = __ldg((const ulonglong2*)(wp + k * 128));
        acc.a00 = fma2(a.x, w.x, acc.a00);
        acc.a01 = fma2(a.x, w.y, acc.a01);
        acc.a10 = fma2(a.y, w.x, acc.a10);
        acc.a11 = fma2(a.y, w.y, acc.a11);
    }
    return acc;
}

// k-split (16 warps): warp = (rowpair rp, k-quarter kq), 32 k's each
DEV Acc4 gemm_ks(const float* __restrict__ ATs, const float* __restrict__ W,
                 int lane, int rp, int kq) {
    const float* ap = ATs + kq * 32 * 20 + rp * 4;
    const float* wp = W + kq * 32 * 128 + lane * 4;
    Acc4 acc; acc.a00 = acc.a01 = acc.a10 = acc.a11 = 0ull;
#pragma unroll 8
    for (int k = 0; k < 32; k++) {
        ulonglong2 a = *(const ulonglong2*)(ap + k * 20);
        ulonglong2 w = __ldg((const ulonglong2*)(wp + k * 128));
        acc.a00 = fma2(a.x, w.x, acc.a00);
        acc.a01 = fma2(a.x, w.y, acc.a01);
        acc.a10 = fma2(a.y, w.x, acc.a10);
        acc.a11 = fma2(a.y, w.y, acc.a11);
    }
    return acc;
}

DEV void store_part(float* sPart, Acc4 acc, int lane, int rp, int kq) {
    float v0, v1, v2, v3;
    upk(acc.a00, v0, v1); upk(acc.a01, v2, v3);
    *(float4*)(sPart + (kq * 8 + 2 * rp) * 128 + lane * 4) = make_float4(v0, v1, v2, v3);
    upk(acc.a10, v0, v1); upk(acc.a11, v2, v3);
    *(float4*)(sPart + (kq * 8 + 2 * rp + 1) * 128 + lane * 4) = make_float4(v0, v1, v2, v3);
}

// ---------------- smem layout (floats) ----------------
// sPj    [0, 32768)      full Pj slab for this batch (256 x 128)
// sPart  [32768, 36864)  k-split / j-quarter partials (4 x 8 x 128)
// sATs   [36864, 39424)  dup'd A tile (128 x 20)
// sNTs   [39424, 41984)  dup'd NH tile
// sPi    [41984, 43008)  own-rows Pi (8 x 128)
// sPn    [43008, 44032)  own-rows Pn
// sAdj2  [44032, 48128)  dup'd adjacency [256 j][16]  (layer-invariant)
// s_rs   [48128, 48136)  own-rows rowsum
static constexpr int SMEM_FLOATS = 48136;

__global__ void __launch_bounds__(NT, 1) k_main(
    float* __restrict__ x, const float* __restrict__ nf, const float* __restrict__ adj,
    const float* __restrict__ ew1, const float* __restrict__ eb1,
    const float* __restrict__ ew2, const float* __restrict__ eb2,
    const float* __restrict__ nw1, const float* __restrict__ nb1,
    const float* __restrict__ nw2, const float* __restrict__ nb2) {
    extern __shared__ float sm[];
    float* sPj = sm;
    float* sPart = sm + 32768;
    float* sATs = sm + 36864;
    float* sNTs = sm + 39424;
    float* sPi = sm + 41984;
    float* sPn = sm + 43008;
    float* sAdj2 = sm + 44032;
    float* s_rs = sm + 48128;

    int tid = threadIdx.x, lane = tid & 31, w = tid >> 5;
    int rb = blockIdx.x;            // rows rb*8 .. rb*8+7
    int b = rb >> 5;                // batch
    int il0 = (rb & 31) * 8;        // local i base in batch

    // ================= phase 0: setup =================
    {   // x = node_features (own rows)
        const float4* src = (const float4*)(nf + rb * 8 * 128);
        float4* dst = (float4*)(x + rb * 8 * 128);
        for (int i = tid; i < 256; i += NT) dst[i] = src[i];
    }
    const float* adjb = adj + (size_t)(b * 256 + il0) * 256;
#pragma unroll
    for (int e = 0; e < 4; e++) {   // dup'd adjacency into smem (persists all layers)
        int idx = e * NT + tid;
        int r = idx >> 8, j = idx & 255;
        float v = adjb[r * 256 + j];
        sAdj2[j * 16 + 2 * r] = v;
        sAdj2[j * 16 + 2 * r + 1] = v;
    }
    if (w < 8) {                    // rowsum (own rows)
        float s = 0.f;
        const float* row = adjb + w * 256;
#pragma unroll
        for (int j = lane; j < 256; j += 32) s += row[j];
#pragma unroll
        for (int o = 16; o; o >>= 1) s += __shfl_xor_sync(~0u, s, o);
        if (!lane) s_rs[w] = s;
    }
    if (rb < 48) {                  // Wc[l] = ew2[l] @ nw1b[l]  (48 units of 8 rows)
        int l = rb / 16, r8 = rb % 16;
        const float* A = ew2 + l * 128 * 128 + r8 * 8 * 128;
        const float* W = nw1 + l * 2 * 128 * 128 + 128 * 128;
#pragma unroll
        for (int q = 0; q < 2; q++) {
            int idx = q * NT + tid;
            int r = idx >> 7, k = idx & 127;
            float v = A[r * 128 + k];
            sATs[k * 20 + 2 * r] = v;
            sATs[k * 20 + 2 * r + 1] = v;
        }
        __syncthreads();
        Acc4 acc = gemm_ks(sATs, W, lane, w & 3, w >> 2);
        store_part(sPart, acc, lane, w & 3, w >> 2);
        __syncthreads();
#pragma unroll
        for (int q = 0; q < 2; q++) {
            int o = q * NT + tid;
            int r = o >> 7, c = o & 127;
            float v = sPart[r * 128 + c] + sPart[(8 + r) * 128 + c] +
                      sPart[(16 + r) * 128 + c] + sPart[(24 + r) * 128 + c];
            g_Wc[l][(r8 * 8 + r) * 128 + c] = v;
        }
    } else if (rb == 48) {          // cb[l] = eb2[l] @ nw1b[l]
        if (tid < 384) {
            int l = tid >> 7, c = tid & 127;
            const float* e2 = eb2 + l * 128;
            const float* W = nw1 + l * 2 * 128 * 128 + 128 * 128 + c;
            float s = 0.f;
#pragma unroll 8
            for (int m = 0; m < 128; m++) s = fmaf(e2[m], W[m * 128], s);
            g_cb[l][c] = s;
        }
    }
    grid_barrier(0, tid);

    // ================= layers =================
    for (int l = 0; l < L_; l++) {
        float* Pbuf = g_P[l & 1];

        // ---- phase A: proj (3 teams x 128 thr; Pi/Pn stay in smem) ----
#pragma unroll
        for (int q = 0; q < 2; q++) {
            int idx = q * NT + tid;
            int r = idx >> 7, k = idx & 127;
            float v = x[(rb * 8 + r) * 128 + k];
            sATs[k * 20 + 2 * r] = v;
            sATs[k * 20 + 2 * r + 1] = v;
        }
        __syncthreads();
        int team = tid >> 7, ttid = tid & 127;
        if (team < 3) {
            const float* W; const float* bias = nullptr;
            if (team == 0)      { W = ew1 + l * 2 * 128 * 128;             bias = eb1 + l * 128; }
            else if (team == 1) { W = ew1 + l * 2 * 128 * 128 + 128 * 128; }
            else                { W = nw1 + l * 2 * 128 * 128;             bias = nb1 + l * 128; }
            Acc4 acc = gemm8(sATs, W, ttid);
            int tl = ttid & 31, r0 = (ttid >> 5) * 2;
            u64 b01 = 0ull, b23 = 0ull;
            if (bias) { ulonglong2 bv = *(const ulonglong2*)(bias + tl * 4); b01 = bv.x; b23 = bv.y; }
            ulonglong2 o0, o1;
            o0.x = add2(acc.a00, b01); o0.y = add2(acc.a01, b23);
            o1.x = add2(acc.a10, b01); o1.y = add2(acc.a11, b23);
            if (team == 1) {
                float* base = Pbuf + (rb * 8 + r0) * 128 + tl * 4;
                *(ulonglong2*)base = o0;
                *(ulonglong2*)(base + 128) = o1;
            } else {
                float* base = (team == 0 ? sPi : sPn) + r0 * 128 + tl * 4;
                *(ulonglong2*)base = o0;
                *(ulonglong2*)(base + 128) = o1;
            }
        }
        grid_barrier(1 + l, tid);

        // ---- phase B: agg + nh + upd (all smem-local) ----
        {   // stage full Pj slab for this batch (128KB from L2)
            const float4* src = (const float4*)(Pbuf + b * 256 * 128);
            float4* dst = (float4*)sPj;
            for (int i = tid; i < 8192; i += NT) dst[i] = src[i];
        }
        __syncthreads();

        {   // agg: warp = (i-pair p, j-quarter jq), 64 j's each
            int p = w & 3, jq = w >> 2;
            ulonglong2 v0 = *(const ulonglong2*)(sPi + (2 * p) * 128 + lane * 4);
            ulonglong2 v1 = *(const ulonglong2*)(sPi + (2 * p + 1) * 128 + lane * 4);
            u64 xi00 = v0.x, xi01 = v0.y, xi10 = v1.x, xi11 = v1.y;
            u64 a00 = 0ull, a01 = 0ull, a10 = 0ull, a11 = 0ull;
            const float* pj = sPj + jq * 64 * 128 + lane * 4;
            const float* ad = sAdj2 + jq * 64 * 16 + p * 4;
#pragma unroll 8
            for (int jj = 0; jj < 64; jj++) {
                ulonglong2 xj = *(const ulonglong2*)(pj + jj * 128);
                ulonglong2 aa = *(const ulonglong2*)(ad + jj * 16);
                u64 t;
                t = relu2(add2(xi00, xj.x)); a00 = fma2(t, aa.x, a00);
                t = relu2(add2(xi01, xj.y)); a01 = fma2(t, aa.x, a01);
                t = relu2(add2(xi10, xj.x)); a10 = fma2(t, aa.y, a10);
                t = relu2(add2(xi11, xj.y)); a11 = fma2(t, aa.y, a11);
            }
            float u0, u1, u2, u3;
            upk(a00, u0, u1); upk(a01, u2, u3);
            *(float4*)(sPart + (jq * 8 + 2 * p) * 128 + lane * 4) = make_float4(u0, u1, u2, u3);
            upk(a10, u0, u1); upk(a11, u2, u3);
            *(float4*)(sPart + (jq * 8 + 2 * p + 1) * 128 + lane * 4) = make_float4(u0, u1, u2, u3);
        }
        __syncthreads();
#pragma unroll
        for (int q = 0; q < 2; q++) {   // reduce agg -> dup'd sATs
            int o = q * NT + tid;
            int r = o >> 7, c = o & 127;
            float v = sPart[r * 128 + c] + sPart[(8 + r) * 128 + c] +
                      sPart[(16 + r) * 128 + c] + sPart[(24 + r) * 128 + c];
            sATs[c * 20 + 2 * r] = v;
            sATs[c * 20 + 2 * r + 1] = v;
        }
        __syncthreads();

        {   // nh GEMM: agg @ Wc (k-split 4)
            Acc4 acc = gemm_ks(sATs, g_Wc[l], lane, w & 3, w >> 2);
            store_part(sPart, acc, lane, w & 3, w >> 2);
        }
        __syncthreads();
#pragma unroll
        for (int q = 0; q < 2; q++) {   // reduce + nh epilogue -> dup'd sNTs
            int o = q * NT + tid;
            int r = o >> 7, c = o & 127;
            float v = sPart[r * 128 + c] + sPart[(8 + r) * 128 + c] +
                      sPart[(16 + r) * 128 + c] + sPart[(24 + r) * 128 + c];
            v += sPn[r * 128 + c] + s_rs[r] * g_cb[l][c];
            v = fmaxf(v, 0.f);
            sNTs[c * 20 + 2 * r] = v;
            sNTs[c * 20 + 2 * r + 1] = v;
        }
        __syncthreads();

        {   // upd GEMM: NH @ nw2 (k-split 4)
            Acc4 acc = gemm_ks(sNTs, nw2 + l * 128 * 128, lane, w & 3, w >> 2);
            store_part(sPart, acc, lane, w & 3, w >> 2);
        }
        __syncthreads();
#pragma unroll
        for (int q = 0; q < 2; q++) {   // reduce + residual update
            int o = q * NT + tid;
            int r = o >> 7, c = o & 127;
            float v = sPart[r * 128 + c] + sPart[(8 + r) * 128 + c] +
                      sPart[(16 + r) * 128 + c] + sPart[(24 + r) * 128 + c];
            x[(rb * 8 + r) * 128 + c] += v + nb2[l * 128 + c];
        }
        __syncthreads();   // x + sATs reuse next layer
    }
}

// ---------------- launch ----------------
extern "C" void kernel_launch(void* const* d_in, const int* in_sizes, int n_in,
                              void* d_out, int out_size) {
    const float* nf  = (const float*)d_in[0];
    const float* adj = (const float*)d_in[1];
    const float* ew1 = (const float*)d_in[2];
    const float* eb1 = (const float*)d_in[3];
    const float* ew2 = (const float*)d_in[4];
    const float* eb2 = (const float*)d_in[5];
    const float* nw1 = (const float*)d_in[6];
    const float* nb1 = (const float*)d_in[7];
    const float* nw2 = (const float*)d_in[8];
    const float* nb2 = (const float*)d_in[9];
    float* x = (float*)d_out;

    const int SMEM = SMEM_FLOATS * 4;  // 192544 B
    cudaFuncSetAttribute(k_main, cudaFuncAttributeMaxDynamicSharedMemorySize, SMEM);
    k_main<<<NB, NT, SMEM>>>(x, nf, adj, ew1, eb1, ew2, eb2, nw1, nb1, nw2, nb2);
}

// round 5
// speedup vs baseline: 3.2566x; 1.0212x over previous
#include <cuda_runtime.h>
#include <cstdint>

typedef unsigned long long u64;
#define DEV static __device__ __forceinline__

static constexpr int L_ = 3;
static constexpr int NB = 128;   // 128 CTAs, 8 rows each
static constexpr int NT = 512;   // 16 warps

// ---------------- device globals ----------------
__device__ float g_P[2][1024 * 128];   // double-buffered Pj
__device__ float g_Wc[L_][128 * 128];  // ew2 @ nw1b
__device__ float g_cb[L_][128];        // eb2 @ nw1b
__device__ unsigned g_bar[4];          // monotonic barrier counters (replay-safe)

// ---------------- f32x2 helpers ----------------
DEV u64 pk(float lo, float hi) {
    u64 r; asm("mov.b64 %0,{%1,%2};" : "=l"(r) : "f"(lo), "f"(hi)); return r;
}
DEV void upk(u64 v, float& lo, float& hi) {
    asm("mov.b64 {%0,%1},%2;" : "=f"(lo), "=f"(hi) : "l"(v));
}
DEV u64 add2(u64 a, u64 b) {
    u64 r; asm("add.rn.f32x2 %0,%1,%2;" : "=l"(r) : "l"(a), "l"(b)); return r;
}
DEV u64 fma2(u64 a, u64 b, u64 c) {
    u64 r; asm("fma.rn.f32x2 %0,%1,%2,%3;" : "=l"(r) : "l"(a), "l"(b), "l"(c)); return r;
}
DEV u64 relu2(u64 v) {
    float lo, hi; upk(v, lo, hi);
    return pk(fmaxf(lo, 0.f), fmaxf(hi, 0.f));
}

// ---------------- cp.async helpers ----------------
DEV void cpa16(void* dst, const void* src) {
    unsigned d = (unsigned)__cvta_generic_to_shared(dst);
    asm volatile("cp.async.cg.shared.global [%0],[%1],16;" :: "r"(d), "l"(src) : "memory");
}
DEV void cpa_commit() { asm volatile("cp.async.commit_group;" ::: "memory"); }
DEV void cpa_wait0() { asm volatile("cp.async.wait_group 0;" ::: "memory"); }
DEV void cpa_wait1() { asm volatile("cp.async.wait_group 1;" ::: "memory"); }

// stage 64KB (16384 floats) with all 512 threads, one commit group
DEV void stage64(float* dst, const float* src, int tid) {
#pragma unroll
    for (int i = 0; i < 8; i++)
        cpa16(dst + (i * 512 + tid) * 4, src + (i * 512 + tid) * 4);
    cpa_commit();
}

// ---------------- grid barrier (monotonic counter; replay-safe) ----------------
DEV unsigned ld_acq(const unsigned* p) {
    unsigned v;
    asm volatile("ld.acquire.gpu.global.u32 %0,[%1];" : "=r"(v) : "l"(p) : "memory");
    return v;
}
DEV void grid_barrier(int bidx, int tid) {
    __syncthreads();
    if (tid == 0) {
        __threadfence();
        unsigned t = atomicAdd(&g_bar[bidx], 1u);
        unsigned target = (t / (unsigned)NB + 1u) * (unsigned)NB;
        while (ld_acq(&g_bar[bidx]) < target) { __nanosleep(64); }
        __threadfence();
    }
    __syncthreads();
}

// ---------------- r=4 k-split-8 GEMM (W in smem) ----------------
// warp = (rg = w&1 rowgroup of 4, kq = w>>1 of 8, 16 k each), lane = 4 cols.
// dup'd A layout: ATs[k*20 + 2r] = ATs[k*20+2r+1] = A[r][k]
DEV void gemm_r4k8(const float* __restrict__ ATs, const float* __restrict__ Wsm,
                   int lane, int rg, int kq, u64 acc[4][2]) {
    const float* ap = ATs + kq * 16 * 20 + rg * 8;
    const float* wp = Wsm + kq * 16 * 128 + lane * 4;
#pragma unroll 8
    for (int k = 0; k < 16; k++) {
        ulonglong2 a01 = *(const ulonglong2*)(ap + k * 20);
        ulonglong2 a23 = *(const ulonglong2*)(ap + k * 20 + 4);
        ulonglong2 wv = *(const ulonglong2*)(wp + k * 128);
        acc[0][0] = fma2(a01.x, wv.x, acc[0][0]);
        acc[0][1] = fma2(a01.x, wv.y, acc[0][1]);
        acc[1][0] = fma2(a01.y, wv.x, acc[1][0]);
        acc[1][1] = fma2(a01.y, wv.y, acc[1][1]);
        acc[2][0] = fma2(a23.x, wv.x, acc[2][0]);
        acc[2][1] = fma2(a23.x, wv.y, acc[2][1]);
        acc[3][0] = fma2(a23.y, wv.x, acc[3][0]);
        acc[3][1] = fma2(a23.y, wv.y, acc[3][1]);
    }
}

DEV void store_part8(float* sPart, const u64 acc[4][2], int lane, int rg, int kq) {
    float* o = sPart + kq * 1024 + rg * 4 * 128 + lane * 4;
#pragma unroll
    for (int r = 0; r < 4; r++) {
        float v0, v1, v2, v3;
        upk(acc[r][0], v0, v1); upk(acc[r][1], v2, v3);
        *(float4*)(o + r * 128) = make_float4(v0, v1, v2, v3);
    }
}

DEV float reduce8(const float* __restrict__ sPart, int idx) {
    float v = 0.f;
#pragma unroll
    for (int p = 0; p < 8; p++) v += sPart[p * 1024 + idx];
    return v;
}

// ---------------- agg half: acc += sum_j adj * relu(Pi + Pj) over 16 j ----------------
DEV void agg_half(const float* __restrict__ Pjh, const float* __restrict__ adjh,
                  const u64 xi[4][2], u64 acc[4][2], int lane, int ig, int jq) {
    const float* pj = Pjh + jq * 16 * 128 + lane * 4;
    const float* ad = adjh + jq * 16 * 16 + ig * 8;
#pragma unroll 4
    for (int jj = 0; jj < 16; jj++) {
        ulonglong2 xj = *(const ulonglong2*)(pj + jj * 128);
        ulonglong2 a01 = *(const ulonglong2*)(ad + jj * 16);
        ulonglong2 a23 = *(const ulonglong2*)(ad + jj * 16 + 4);
        u64 t;
        t = relu2(add2(xi[0][0], xj.x)); acc[0][0] = fma2(t, a01.x, acc[0][0]);
        t = relu2(add2(xi[0][1], xj.y)); acc[0][1] = fma2(t, a01.x, acc[0][1]);
        t = relu2(add2(xi[1][0], xj.x)); acc[1][0] = fma2(t, a01.y, acc[1][0]);
        t = relu2(add2(xi[1][1], xj.y)); acc[1][1] = fma2(t, a01.y, acc[1][1]);
        t = relu2(add2(xi[2][0], xj.x)); acc[2][0] = fma2(t, a23.x, acc[2][0]);
        t = relu2(add2(xi[2][1], xj.y)); acc[2][1] = fma2(t, a23.x, acc[2][1]);
        t = relu2(add2(xi[3][0], xj.x)); acc[3][0] = fma2(t, a23.y, acc[3][0]);
        t = relu2(add2(xi[3][1], xj.y)); acc[3][1] = fma2(t, a23.y, acc[3][1]);
    }
}

// ---------------- smem layout (floats) ----------------
// b0 0 (16384) | b1 16384 (16384) | sPart 32768 (8192) | sATs 40960 (2560)
// sNTs 43520 (2560) | sPi 46080 (1024) | sPn 47104 (1024) | sAdj2 48128 (4096)
// s_rs 52224 (8) | sX 52232 (1024)
static constexpr int SMEM_FLOATS = 53256;   // 213024 B

__global__ void __launch_bounds__(NT, 1) k_main(
    float* __restrict__ x, const float* __restrict__ nf, const float* __restrict__ adj,
    const float* __restrict__ ew1, const float* __restrict__ eb1,
    const float* __restrict__ ew2, const float* __restrict__ eb2,
    const float* __restrict__ nw1, const float* __restrict__ nb1,
    const float* __restrict__ nw2, const float* __restrict__ nb2) {
    extern __shared__ float sm[];
    float* b0 = sm;
    float* b1 = sm + 16384;
    float* sPart = sm + 32768;
    float* sATs = sm + 40960;
    float* sNTs = sm + 43520;
    float* sPi = sm + 46080;
    float* sPn = sm + 47104;
    float* sAdj2 = sm + 48128;
    float* s_rs = sm + 52224;
    float* sX = sm + 52232;

    int tid = threadIdx.x, lane = tid & 31, w = tid >> 5;
    int rb = blockIdx.x;        // rows rb*8 .. rb*8+7
    int b = rb >> 5;            // batch
    int il0 = (rb & 31) * 8;    // local i base in batch
    int rg = w & 1, kq = w >> 1;   // gemm warp roles
    int ig = w & 1, jq = w >> 1;   // agg warp roles
    int rr = tid >> 7, cc = tid & 127;   // reduce/epilogue roles (q adds 4 to rr)

    // ================= setup =================
#pragma unroll
    for (int q = 0; q < 2; q++) sX[q * 512 + tid] = nf[rb * 1024 + q * 512 + tid];

    const float* adjb = adj + (size_t)(b * 256 + il0) * 256;
#pragma unroll
    for (int e = 0; e < 4; e++) {
        int idx = e * 512 + tid;
        int r = idx >> 8, j = idx & 255;
        float v = adjb[r * 256 + j];
        sAdj2[j * 16 + 2 * r] = v;
        sAdj2[j * 16 + 2 * r + 1] = v;
    }
    if (w < 8) {
        float s = 0.f;
        const float* row = adjb + w * 256;
#pragma unroll
        for (int j = lane; j < 256; j += 32) s += row[j];
#pragma unroll
        for (int o = 16; o; o >>= 1) s += __shfl_xor_sync(~0u, s, o);
        if (!lane) s_rs[w] = s;
    }
    if (rb < 48) {   // Wc[l] = ew2[l] @ nw1b[l]
        int l = rb / 16, r8 = rb % 16;
        stage64(b0, nw1 + l * 32768 + 16384, tid);
#pragma unroll
        for (int q = 0; q < 2; q++) {
            int idx = q * 512 + tid;
            int r = idx >> 7, k = idx & 127;
            float v = ew2[l * 16384 + (r8 * 8 + r) * 128 + k];
            sATs[k * 20 + 2 * r] = v;
            sATs[k * 20 + 2 * r + 1] = v;
        }
        cpa_wait0();
        __syncthreads();
        u64 acc[4][2] = {};
        gemm_r4k8(sATs, b0, lane, rg, kq, acc);
        store_part8(sPart, acc, lane, rg, kq);
        __syncthreads();
#pragma unroll
        for (int q = 0; q < 2; q++) {
            int idx = q * 512 + tid;
            g_Wc[l][(r8 * 8 + rr + q * 4) * 128 + cc] = reduce8(sPart, idx);
        }
    } else if (rb == 48) {
        if (tid < 384) {
            int l = tid >> 7, c = tid & 127;
            const float* e2 = eb2 + l * 128;
            const float* W = nw1 + l * 32768 + 16384 + c;
            float s = 0.f;
#pragma unroll 8
            for (int m = 0; m < 128; m++) s = fmaf(e2[m], W[m * 128], s);
            g_cb[l][c] = s;
        }
        cpa_wait0();
    } else {
        cpa_wait0();
    }
    grid_barrier(0, tid);

    // prefetch ew1a (layer 0)
    stage64(b0, ew1 + 0, tid);

    // ================= layers =================
    for (int l = 0; l < L_; l++) {
        float* Pbuf = g_P[l & 1];
        const float* ew1l = ew1 + l * 32768;

        stage64(b1, ew1l + 16384, tid);            // ew1b
#pragma unroll
        for (int q = 0; q < 2; q++) {              // sX -> dup'd sATs
            int idx = q * 512 + tid;
            int r = idx >> 7, k = idx & 127;
            float v = sX[idx];
            sATs[k * 20 + 2 * r] = v;
            sATs[k * 20 + 2 * r + 1] = v;
        }
        cpa_wait1();        // ew1a (b0) landed
        __syncthreads();

        // ---- proj a: Pi = x @ ew1a + eb1 ----
        {
            u64 acc[4][2] = {};
            gemm_r4k8(sATs, b0, lane, rg, kq, acc);
            store_part8(sPart, acc, lane, rg, kq);
            __syncthreads();                        // b0 free, sPart ready
            stage64(b0, nw1 + l * 32768, tid);      // nw1a -> b0
            float bv = eb1[l * 128 + cc];
#pragma unroll
            for (int q = 0; q < 2; q++) {
                int idx = q * 512 + tid;
                sPi[(rr + q * 4) * 128 + cc] = reduce8(sPart, idx) + bv;
            }
            cpa_wait1();    // ew1b (b1) landed
            __syncthreads();
        }
        // ---- proj b: Pj = x @ ew1b -> global ----
        {
            u64 acc[4][2] = {};
            gemm_r4k8(sATs, b1, lane, rg, kq, acc);
            store_part8(sPart, acc, lane, rg, kq);
            __syncthreads();
#pragma unroll
            for (int q = 0; q < 2; q++) {
                int idx = q * 512 + tid;
                Pbuf[(rb * 8 + rr + q * 4) * 128 + cc] = reduce8(sPart, idx);
            }
            cpa_wait0();    // nw1a (b0) landed
            __syncthreads();
        }
        // ---- proj n: Pn = x @ nw1a + nb1 ----
        {
            u64 acc[4][2] = {};
            gemm_r4k8(sATs, b0, lane, rg, kq, acc);
            store_part8(sPart, acc, lane, rg, kq);
            __syncthreads();
            float bv = nb1[l * 128 + cc];
#pragma unroll
            for (int q = 0; q < 2; q++) {
                int idx = q * 512 + tid;
                sPn[(rr + q * 4) * 128 + cc] = reduce8(sPart, idx) + bv;
            }
            __syncthreads();
        }

        grid_barrier(1 + l, tid);   // Pj globally visible

        stage64(b0, Pbuf + b * 32768, tid);            // Pj half0
        stage64(b1, Pbuf + b * 32768 + 16384, tid);    // Pj half1

        // ---- agg (acc persists across halves) ----
        u64 xi[4][2], aacc[4][2] = {};
#pragma unroll
        for (int q = 0; q < 4; q++) {
            ulonglong2 v = *(const ulonglong2*)(sPi + (ig * 4 + q) * 128 + lane * 4);
            xi[q][0] = v.x; xi[q][1] = v.y;
        }
        cpa_wait1();        // Pj half0 landed
        __syncthreads();
        agg_half(b0, sAdj2, xi, aacc, lane, ig, jq);
        __syncthreads();                            // b0 free
        stage64(b0, g_Wc[l], tid);                  // Wc -> b0
        cpa_wait1();        // Pj half1 landed
        __syncthreads();
        agg_half(b1, sAdj2 + 128 * 16, xi, aacc, lane, ig, jq);
        {   // store agg partials (p = jq)
            float* o = sPart + jq * 1024 + ig * 4 * 128 + lane * 4;
#pragma unroll
            for (int q = 0; q < 4; q++) {
                float v0, v1, v2, v3;
                upk(aacc[q][0], v0, v1); upk(aacc[q][1], v2, v3);
                *(float4*)(o + q * 128) = make_float4(v0, v1, v2, v3);
            }
        }
        __syncthreads();                            // b1 free, sPart ready
        stage64(b1, nw2 + l * 16384, tid);          // nw2 -> b1
#pragma unroll
        for (int q = 0; q < 2; q++) {               // reduce agg -> dup'd sATs
            int idx = q * 512 + tid;
            float v = reduce8(sPart, idx);
            sATs[cc * 20 + 2 * (rr + q * 4)] = v;
            sATs[cc * 20 + 2 * (rr + q * 4) + 1] = v;
        }
        cpa_wait1();        // Wc (b0) landed
        __syncthreads();

        // ---- nh = relu(Pn + agg@Wc + rs*cb) ----
        {
            u64 acc[4][2] = {};
            gemm_r4k8(sATs, b0, lane, rg, kq, acc);
            store_part8(sPart, acc, lane, rg, kq);
            __syncthreads();                        // b0 free
            float cbv = g_cb[l][cc];
#pragma unroll
            for (int q = 0; q < 2; q++) {
                int idx = q * 512 + tid;
                int r = rr + q * 4;
                float v = reduce8(sPart, idx) + sPn[r * 128 + cc] + s_rs[r] * cbv;
                v = fmaxf(v, 0.f);
                sNTs[cc * 20 + 2 * r] = v;
                sNTs[cc * 20 + 2 * r + 1] = v;
            }
            __syncthreads();
        }
        stage64(b0, ew1 + (l + 1 < L_ ? l + 1 : 0) * 32768, tid);  // next ew1a
        cpa_wait1();        // nw2 (b1) landed
        __syncthreads();

        // ---- x += nh @ nw2 + nb2 ----
        {
            u64 acc[4][2] = {};
            gemm_r4k8(sNTs, b1, lane, rg, kq, acc);
            store_part8(sPart, acc, lane, rg, kq);
            __syncthreads();
            float bv = nb2[l * 128 + cc];
#pragma unroll
            for (int q = 0; q < 2; q++) {
                int idx = q * 512 + tid;
                float v = sX[idx] + reduce8(sPart, idx) + bv;
                sX[idx] = v;
                if (l == L_ - 1) x[rb * 1024 + idx] = v;
            }
            __syncthreads();
        }
    }
    cpa_wait0();
}

// ---------------- launch ----------------
extern "C" void kernel_launch(void* const* d_in, const int* in_sizes, int n_in,
                              void* d_out, int out_size) {
    const float* nf  = (const float*)d_in[0];
    const float* adj = (const float*)d_in[1];
    const float* ew1 = (const float*)d_in[2];
    const float* eb1 = (const float*)d_in[3];
    const float* ew2 = (const float*)d_in[4];
    const float* eb2 = (const float*)d_in[5];
    const float* nw1 = (const float*)d_in[6];
    const float* nb1 = (const float*)d_in[7];
    const float* nw2 = (const float*)d_in[8];
    const float* nb2 = (const float*)d_in[9];
    float* x = (float*)d_out;

    const int SMEM = SMEM_FLOATS * 4;   // 213024 B
    cudaFuncSetAttribute(k_main, cudaFuncAttributeMaxDynamicSharedMemorySize, SMEM);
    k_main<<<NB, NT, SMEM>>>(x, nf, adj, ew1, eb1, ew2, eb2, nw1, nb1, nw2, nb2);
}